// round 15
// baseline (speedup 1.0000x reference)
#include <cuda_runtime.h>
#include <cuda_fp16.h>
#include <cstdint>

#define BB 2
#define NN 256
#define EE 512
#define HH 150
#define HP 160

// smem map (bytes)
#define SM_A    0        // A int8 resident [64 x 512B swz] = 32768
#define SM_STG  32768    // B stages: 2 x [160 x 128B swz] = 40960 (end 73728)
#define STG_SZ  20480
#define SM_W2   0        // phase2: W2T fp16 [160 x 336B] = 53760 (reuses A+stages)
#define SM_HF   53760    // 64 x 336B = 21504
#define SM_HT   75264    // 21504 (end 96768)
#define SM_SBW  96768    // fp32[160] W1q row scales
#define SM_SA   97408    // fp32[64]  A row scales
#define SM_HI   97664    // fp32[160]
#define SM_HJC  98304    // fp32[160]
#define SM_B2   98944    // fp32[160]
#define SM_W3   99584    // fp32[160]
#define SM_PRB  100224   // 4 x 64 fp32
#define SMEM_BYTES 101376

// device scratch
__device__ __half  d_gh[BB * NN * EE];    // fp16 g
__device__ __half  d_W1cTh[HP * EE];      // W1c^T fp16 (for w1q)
__device__ __half  d_W2Th[HP * HP];       // W2^T fp16
__device__ uint8_t d_W1q[HP * EE];        // int8 W1c^T, per-row scale d_sw1
__device__ float   d_sw1[HP];
__device__ float   d_hi[BB * NN * HP];
__device__ float   d_hj[BB * NN * HP];
__device__ __half  d_hjh[BB * NN * HP];
__device__ __half  d_hih[BB * NN * HP];

// ---- helpers ----
__device__ __forceinline__ uint32_t h2mul(uint32_t a, uint32_t b) {
    uint32_t r; asm("mul.rn.f16x2 %0, %1, %2;" : "=r"(r) : "r"(a), "r"(b)); return r;
}
__device__ __forceinline__ float2 h2f2(uint32_t h) {
    __half2 v = *reinterpret_cast<__half2*>(&h); return __half22float2(v);
}
__device__ __forceinline__ uint32_t f2h2(float lo, float hi) {
    uint32_t r; asm("cvt.rn.f16x2.f32 %0, %1, %2;" : "=r"(r) : "f"(hi), "f"(lo)); return r;
}
__device__ __forceinline__ void cp16s(uint32_t dst, const void* src) {
    asm volatile("cp.async.cg.shared.global [%0], [%1], 16;" :: "r"(dst), "l"(src));
}
__device__ __forceinline__ void sts32(uint32_t a, uint32_t v) {
    asm volatile("st.shared.b32 [%0], %1;" :: "r"(a), "r"(v));
}
__device__ __forceinline__ void sts128(uint32_t a, uint32_t x, uint32_t y,
                                       uint32_t z, uint32_t w) {
    asm volatile("st.shared.v4.b32 [%0], {%1,%2,%3,%4};"
                 :: "r"(a), "r"(x), "r"(y), "r"(z), "r"(w));
}
#define LDSM4(r0, r1, r2, r3, a)                                              \
    asm volatile("ldmatrix.sync.aligned.m8n8.x4.shared.b16 {%0,%1,%2,%3}, [%4];" \
                 : "=r"(r0), "=r"(r1), "=r"(r2), "=r"(r3) : "r"(a))
#define LDSM2(r0, r1, a)                                                      \
    asm volatile("ldmatrix.sync.aligned.m8n8.x2.shared.b16 {%0,%1}, [%2];"    \
                 : "=r"(r0), "=r"(r1) : "r"(a))
__device__ __forceinline__ void mma16(float* d, const uint32_t* a, const uint32_t* b) {
    asm volatile("mma.sync.aligned.m16n8k16.row.col.f32.f16.f16.f32 "
                 "{%0,%1,%2,%3},{%4,%5,%6,%7},{%8,%9},{%0,%1,%2,%3};"
                 : "+f"(d[0]), "+f"(d[1]), "+f"(d[2]), "+f"(d[3])
                 : "r"(a[0]), "r"(a[1]), "r"(a[2]), "r"(a[3]), "r"(b[0]), "r"(b[1]));
}
__device__ __forceinline__ void imma32(int* d, const uint32_t* a, const uint32_t* b) {
    asm volatile("mma.sync.aligned.m16n8k32.row.col.s32.s8.s8.s32 "
                 "{%0,%1,%2,%3},{%4,%5,%6,%7},{%8,%9},{%0,%1,%2,%3};"
                 : "+r"(d[0]), "+r"(d[1]), "+r"(d[2]), "+r"(d[3])
                 : "r"(a[0]), "r"(a[1]), "r"(a[2]), "r"(a[3]), "r"(b[0]), "r"(b[1]));
}
__device__ __forceinline__ uint32_t pack4(int a, int bq, int c, int d) {
    return (uint32_t)(a & 255) | ((uint32_t)(bq & 255) << 8) |
           ((uint32_t)(c & 255) << 16) | ((uint32_t)d << 24);
}

// ---------------------------------------------------------------------------
__global__ void prep_kernel(const float* __restrict__ g, const float* __restrict__ W1,
                            const float* __restrict__ W2) {
    const int S0 = BB * NN * EE, S1 = HP * EE, S2 = HP * HP;
    const int total = S0 + S1 + S2;
    for (int idx = blockIdx.x * blockDim.x + threadIdx.x; idx < total;
         idx += gridDim.x * blockDim.x) {
        int t = idx;
        if (t < S0) { d_gh[t] = __float2half(g[t]); continue; }
        t -= S0;
        if (t < S1) {
            int n = t >> 9, k = t & 511;
            d_W1cTh[t] = (n < HH) ? __float2half(W1[(size_t)(2 * EE + k) * HH + n])
                                  : __float2half(0.f);
            continue;
        }
        t -= S1;
        {
            int n = t / HP, k = t % HP;
            d_W2Th[t] = (n < HH && k < HH) ? __float2half(W2[(size_t)k * HH + n])
                                           : __float2half(0.f);
        }
    }
}

// int8 quantize of W1cT rows (reads fp16 d_W1cTh). One warp per n row.
__global__ void w1q_kernel() {
    const int n = blockIdx.x, lane = threadIdx.x;
    const uint4* wp = (const uint4*)(d_W1cTh + (size_t)n * EE + lane * 16);
    uint4 wA = wp[0], wB = wp[1];
    uint32_t p[8] = {wA.x, wA.y, wA.z, wA.w, wB.x, wB.y, wB.z, wB.w};
    __half2 mx = __habs2(*(__half2*)&p[0]);
#pragma unroll
    for (int q = 1; q < 8; q++) mx = __hmax2(mx, __habs2(*(__half2*)&p[q]));
    float m = fmaxf(__low2float(mx), __high2float(mx));
#pragma unroll
    for (int s = 16; s >= 1; s >>= 1) m = fmaxf(m, __shfl_xor_sync(~0u, m, s));
    float inv = (m > 0.f) ? 127.f / m : 0.f;
    uint4 o;
    {
        float2 f0 = h2f2(p[0]), f1 = h2f2(p[1]);
        o.x = pack4(__float2int_rn(f0.x * inv), __float2int_rn(f0.y * inv),
                    __float2int_rn(f1.x * inv), __float2int_rn(f1.y * inv));
        f0 = h2f2(p[2]); f1 = h2f2(p[3]);
        o.y = pack4(__float2int_rn(f0.x * inv), __float2int_rn(f0.y * inv),
                    __float2int_rn(f1.x * inv), __float2int_rn(f1.y * inv));
        f0 = h2f2(p[4]); f1 = h2f2(p[5]);
        o.z = pack4(__float2int_rn(f0.x * inv), __float2int_rn(f0.y * inv),
                    __float2int_rn(f1.x * inv), __float2int_rn(f1.y * inv));
        f0 = h2f2(p[6]); f1 = h2f2(p[7]);
        o.w = pack4(__float2int_rn(f0.x * inv), __float2int_rn(f0.y * inv),
                    __float2int_rn(f1.x * inv), __float2int_rn(f1.y * inv));
    }
    *(uint4*)(d_W1q + (size_t)n * EE + lane * 16) = o;
    if (lane == 0) d_sw1[n] = m * (1.f / 127.f);
}

// hihj: 128 blocks (64 rowblocks x 8 rows, 2 halves), full K, no atomics.
__global__ void hihj2_kernel(const float* __restrict__ g, const float* __restrict__ W1,
                             const float* __restrict__ b1) {
    __shared__ float gs[8][65];
    __shared__ float Ws[64][HP];
    const int tid = threadIdx.x;
    const int rb = blockIdx.x, half = blockIdx.y;
    const int row0 = rb * 8;
    const int tx = tid & 31, ty = tid >> 5;

    float acc[5] = {0.f, 0.f, 0.f, 0.f, 0.f};

    for (int kk = 0; kk < 8; kk++) {
        const int kbase = kk * 64;
        for (int q = tid; q < 8 * 64; q += 256) {
            int r = q >> 6, c = q & 63;
            gs[r][c] = g[(size_t)(row0 + r) * EE + kbase + c];
        }
        for (int q = tid; q < 64 * HP; q += 256) {
            int r = q / HP, c = q % HP;
            Ws[r][c] = (c < HH) ? W1[(size_t)(half * 512 + kbase + r) * HH + c] : 0.f;
        }
        __syncthreads();
#pragma unroll 8
        for (int k = 0; k < 64; k++) {
            const float gv = gs[ty][k];
#pragma unroll
            for (int v = 0; v < 5; v++) acc[v] += gv * Ws[k][tx * 5 + v];
        }
        __syncthreads();
    }
    const int row = row0 + ty;
#pragma unroll
    for (int v = 0; v < 5; v++) {
        const int col = tx * 5 + v;
        const size_t off = (size_t)row * HP + col;
        if (half == 0) {
            float val = acc[v] + ((col < HH) ? b1[col] : 0.f);
            d_hi[off] = val;
            d_hih[off] = __float2half(val);
        } else {
            d_hj[off] = acc[v];
            d_hjh[off] = __float2half(acc[v]);
        }
    }
}

// ---------------------------------------------------------------------------
// fused kernel: int8 GEMM1 (A = g_i*g_j built in-CTA + resident; B = int8 W1cT
// streamed, CTA-invariant, L2-hot), fp16 GEMM2, symmetric hij reuse.
// 256 threads, 8 warps 2Mx4N, 2 CTAs/SM.
// ---------------------------------------------------------------------------
__global__ __launch_bounds__(256, 2) void pair_i8(
    const float* __restrict__ ment, const float* __restrict__ b2,
    const float* __restrict__ W3, const float* __restrict__ b3,
    float* __restrict__ out) {
    extern __shared__ __align__(16) unsigned char smem[];
    const uint32_t sb = (uint32_t)__cvta_generic_to_shared(smem);
    float* sbw_s = (float*)(smem + SM_SBW);
    float* sa_s  = (float*)(smem + SM_SA);
    float* hi_s  = (float*)(smem + SM_HI);
    float* hjc_s = (float*)(smem + SM_HJC);
    float* b2_s  = (float*)(smem + SM_B2);
    float* w3_s  = (float*)(smem + SM_W3);
    float* prb   = (float*)(smem + SM_PRB);

    const int tid = threadIdx.x, wid = tid >> 5, lane = tid & 31;
    const int b = blockIdx.z;
    int t = blockIdx.x, jb, i;
    if (t < 64)       { jb = 0; i = t; }
    else if (t < 192) { jb = 1; i = t - 64; }
    else if (t < 384) { jb = 2; i = t - 192; }
    else              { jb = 3; i = t - 384; }
    const int j0 = jb * 64;
    const bool has_t = (i < j0);
    const int wm = wid >> 2, wn = wid & 3, grp = lane >> 2, tig = lane & 3;

    // ---- issue B stages 0,1 (cp.async; overlaps A-build) ----
#pragma unroll
    for (int c = 0; c < 2; c++) {
        const uint32_t stg = sb + SM_STG + c * STG_SZ;
#pragma unroll
        for (int q = 0; q < 5; q++) {
            int p = tid + q * 256;
            int row = p >> 3, seg = p & 7;
            cp16s(stg + row * 128 + ((seg * 16) ^ ((row & 7) << 4)),
                  d_W1q + (size_t)row * EE + c * 128 + seg * 16);
        }
        asm volatile("cp.async.commit_group;");
    }

    // ---- misc vector loads ----
    for (int q = tid; q < HP; q += 256) {
        hi_s[q]  = d_hi[(size_t)(b * NN + i) * HP + q];
        hjc_s[q] = d_hj[(size_t)(b * NN + i) * HP + q];
        b2_s[q]  = (q < HH) ? b2[q] : 0.f;
        w3_s[q]  = (q < HH) ? W3[q] : 0.f;
        sbw_s[q] = d_sw1[q];
    }

    // ---- A-build: row r = quant(g_i ⊙ g_j[r]), 8 rows per warp ----
    {
        const __half* giRow = d_gh + (size_t)(b * NN + i) * EE;
        const uint4* gip = (const uint4*)(giRow + lane * 16);
        const uint4 gA = gip[0], gB = gip[1];
#pragma unroll 2
        for (int rr = 0; rr < 8; rr++) {
            const int row = wid * 8 + rr;
            const uint4* gjp = (const uint4*)(d_gh + (size_t)(b * NN + j0 + row) * EE +
                                              lane * 16);
            uint4 jA = gjp[0], jB = gjp[1];
            uint32_t p[8];
            p[0] = h2mul(jA.x, gA.x); p[1] = h2mul(jA.y, gA.y);
            p[2] = h2mul(jA.z, gA.z); p[3] = h2mul(jA.w, gA.w);
            p[4] = h2mul(jB.x, gB.x); p[5] = h2mul(jB.y, gB.y);
            p[6] = h2mul(jB.z, gB.z); p[7] = h2mul(jB.w, gB.w);
            __half2 mx = __habs2(*(__half2*)&p[0]);
#pragma unroll
            for (int q = 1; q < 8; q++) mx = __hmax2(mx, __habs2(*(__half2*)&p[q]));
            float m = fmaxf(__low2float(mx), __high2float(mx));
#pragma unroll
            for (int s = 16; s >= 1; s >>= 1) m = fmaxf(m, __shfl_xor_sync(~0u, m, s));
            float inv = (m > 0.f) ? 127.f / m : 0.f;
            uint32_t w4[4];
#pragma unroll
            for (int q = 0; q < 4; q++) {
                float2 f0 = h2f2(p[q * 2]), f1 = h2f2(p[q * 2 + 1]);
                w4[q] = pack4(__float2int_rn(f0.x * inv), __float2int_rn(f0.y * inv),
                              __float2int_rn(f1.x * inv), __float2int_rn(f1.y * inv));
            }
            sts128(sb + SM_A + row * 512 + ((lane * 16) ^ ((row & 7) << 4)),
                   w4[0], w4[1], w4[2], w4[3]);
            if (lane == 0) sa_s[row] = m * (1.f / 127.f);
        }
    }

    // fragment addressing (validated in R12)
    const uint32_t armA  = (uint32_t)(wm * 32 + (lane & 7) + ((lane >> 3) & 1) * 8);
    const uint32_t amask = (armA & 7) << 4;
    const uint32_t akof0 = (lane >> 4) * 16;
    const uint32_t brow  = (uint32_t)(wn * 40 + (lane & 7) + ((lane >> 4) & 1) * 8);
    const uint32_t bmask = (brow & 7) << 4;
    const uint32_t bkof0 = ((lane >> 3) & 1) * 16;
    const uint32_t b2row = (uint32_t)(wn * 40 + 32 + (lane & 7));
    const uint32_t b2mask = (b2row & 7) << 4;

    int acci[2][5][4];
#pragma unroll
    for (int x = 0; x < 2; x++)
#pragma unroll
        for (int y = 0; y < 5; y++)
#pragma unroll
            for (int e = 0; e < 4; e++) acci[x][y][e] = 0;

    // ---- GEMM1: 4 chunks (K=128) x 4 k32 IMMA steps ----
#pragma unroll 1
    for (int c = 0; c < 4; c++) {
        if (c < 3) asm volatile("cp.async.wait_group 1;");
        else       asm volatile("cp.async.wait_group 0;");
        __syncthreads();
        const uint32_t stg = sb + SM_STG + (c & 1) * STG_SZ;
        const uint32_t abase = sb + SM_A + armA * 512;
        const uint32_t bbase = stg + brow * 128;
        const uint32_t b2base = stg + b2row * 128;
#pragma unroll
        for (int k2 = 0; k2 < 4; k2++) {
            uint32_t a[2][4], bf[5][2];
            const uint32_t ak = (c * 128 + k2 * 32 + akof0) ^ amask;
            LDSM4(a[0][0], a[0][1], a[0][2], a[0][3], abase + ak);
            LDSM4(a[1][0], a[1][1], a[1][2], a[1][3], abase + 16 * 512 + ak);
            const uint32_t bk = (k2 * 32 + bkof0) ^ bmask;
            LDSM4(bf[0][0], bf[0][1], bf[1][0], bf[1][1], bbase + bk);
            LDSM4(bf[2][0], bf[2][1], bf[3][0], bf[3][1], bbase + 16 * 128 + bk);
            const uint32_t b2k = (k2 * 32 + bkof0) ^ b2mask;
            LDSM2(bf[4][0], bf[4][1], b2base + b2k);
#pragma unroll
            for (int mt = 0; mt < 2; mt++)
#pragma unroll
                for (int nt = 0; nt < 5; nt++) imma32(acci[mt][nt], a[mt], bf[nt]);
        }
        __syncthreads();
        if (c + 2 < 4) {
            const int cn = c + 2;
            const uint32_t stgn = sb + SM_STG + (cn & 1) * STG_SZ;
#pragma unroll
            for (int q = 0; q < 5; q++) {
                int p = tid + q * 256;
                int row = p >> 3, seg = p & 7;
                cp16s(stgn + row * 128 + ((seg * 16) ^ ((row & 7) << 4)),
                      d_W1q + (size_t)row * EE + cn * 128 + seg * 16);
            }
            asm volatile("cp.async.commit_group;");
        }
    }

    // ---- prefetch W2T (overlaps epilogue1) ----
#pragma unroll
    for (int tt = 0; tt < 13; tt++) {
        int q = tid + tt * 256;
        if (q < 3200) {
            int n = q / 20, u = q % 20;
            cp16s(sb + SM_W2 + n * 336 + u * 16, d_W2Th + (size_t)n * HP + u * 8);
        }
    }
    asm volatile("cp.async.commit_group;");

    // ---- epilogue1: dequant + biases + relu -> HF (and HT) fp16 ----
#pragma unroll
    for (int mt = 0; mt < 2; mt++) {
#pragma unroll
        for (int hrow = 0; hrow < 2; hrow++) {
            const int r = wm * 32 + mt * 16 + grp + hrow * 8;
            const float sar = sa_s[r];
            const __half* hjrow = d_hjh + (size_t)(b * NN + j0 + r) * HP;
            const __half* hirow = d_hih + (size_t)(b * NN + j0 + r) * HP;
#pragma unroll
            for (int nt = 0; nt < 5; nt++) {
                const int col = wn * 40 + nt * 8 + 2 * tig;
                const float a0 = (float)acci[mt][nt][hrow * 2 + 0] * sar * sbw_s[col];
                const float a1 = (float)acci[mt][nt][hrow * 2 + 1] * sar * sbw_s[col + 1];
                float2 hjf = h2f2(*(const uint32_t*)(hjrow + col));
                float x0 = fmaxf(a0 + hi_s[col] + hjf.x, 0.f);
                float x1 = fmaxf(a1 + hi_s[col + 1] + hjf.y, 0.f);
                sts32(sb + SM_HF + r * 336 + col * 2, f2h2(x0, x1));
                if (has_t) {
                    float2 hif = h2f2(*(const uint32_t*)(hirow + col));
                    float y0 = fmaxf(a0 + hif.x + hjc_s[col], 0.f);
                    float y1 = fmaxf(a1 + hif.y + hjc_s[col + 1], 0.f);
                    sts32(sb + SM_HT + r * 336 + col * 2, f2h2(y0, y1));
                }
            }
        }
    }
    asm volatile("cp.async.wait_group 0;");
    __syncthreads();

    // ---- GEMM2 (fp16) + epilogue2, fwd then transposed ----
    const uint32_t aoffH = armA * 336 + (lane >> 4) * 16;
    const uint32_t boff4W = brow * 336 + ((lane >> 3) & 1) * 16;
    const uint32_t boff2W = b2row * 336 + ((lane >> 3) & 1) * 16;

#pragma unroll 1
    for (int pass = 0; pass < 2; pass++) {
        if (pass == 1 && !has_t) break;
        const uint32_t hbase = sb + (pass ? SM_HT : SM_HF) + aoffH;
        float acc[2][5][4];
#pragma unroll
        for (int x = 0; x < 2; x++)
#pragma unroll
            for (int y = 0; y < 5; y++)
#pragma unroll
                for (int e = 0; e < 4; e++) acc[x][y][e] = 0.f;
#pragma unroll
        for (int kk = 0; kk < 10; kk++) {
            uint32_t a[2][4], bf[5][2];
            const uint32_t abase = hbase + kk * 32;
            LDSM4(a[0][0], a[0][1], a[0][2], a[0][3], abase);
            LDSM4(a[1][0], a[1][1], a[1][2], a[1][3], abase + 5376);
            const uint32_t bbw = sb + SM_W2 + kk * 32;
            LDSM4(bf[0][0], bf[0][1], bf[1][0], bf[1][1], bbw + boff4W);
            LDSM4(bf[2][0], bf[2][1], bf[3][0], bf[3][1], bbw + boff4W + 5376);
            LDSM2(bf[4][0], bf[4][1], bbw + boff2W);
#pragma unroll
            for (int mt = 0; mt < 2; mt++)
#pragma unroll
                for (int nt = 0; nt < 5; nt++) mma16(acc[mt][nt], a[mt], bf[nt]);
        }
#pragma unroll
        for (int mt = 0; mt < 2; mt++) {
            float s0 = 0.f, s1 = 0.f;
#pragma unroll
            for (int nt = 0; nt < 5; nt++) {
                const int col = wn * 40 + nt * 8 + 2 * tig;
                s0 += fmaxf(acc[mt][nt][0] + b2_s[col], 0.f) * w3_s[col];
                s0 += fmaxf(acc[mt][nt][1] + b2_s[col + 1], 0.f) * w3_s[col + 1];
                s1 += fmaxf(acc[mt][nt][2] + b2_s[col], 0.f) * w3_s[col];
                s1 += fmaxf(acc[mt][nt][3] + b2_s[col + 1], 0.f) * w3_s[col + 1];
            }
            s0 += __shfl_xor_sync(0xffffffffu, s0, 1);
            s0 += __shfl_xor_sync(0xffffffffu, s0, 2);
            s1 += __shfl_xor_sync(0xffffffffu, s1, 1);
            s1 += __shfl_xor_sync(0xffffffffu, s1, 2);
            if (tig == 0) {
                prb[wn * 64 + wm * 32 + mt * 16 + grp] = s0;
                prb[wn * 64 + wm * 32 + mt * 16 + grp + 8] = s1;
            }
        }
        __syncthreads();
        if (tid < 64) {
            const int j = j0 + tid;
            float pair = prb[tid] + prb[64 + tid] + prb[128 + tid] + prb[192 + tid] + b3[0];
            float mi = ment[b * NN + i];
            float mj = ment[b * NN + j];
            float val = (mi + mj + pair) * (1.f / 3.f);
            if (pass == 0) out[(size_t)(b * NN + i) * NN + j] = val;
            else           out[(size_t)(b * NN + j) * NN + i] = val;
        }
        __syncthreads();
    }
}

// ---------------------------------------------------------------------------
extern "C" void kernel_launch(void* const* d_in, const int* in_sizes, int n_in,
                              void* d_out, int out_size) {
    const float* g  = (const float*)d_in[0];
    const float* m  = (const float*)d_in[1];
    const float* W1 = (const float*)d_in[2];
    const float* b1 = (const float*)d_in[3];
    const float* W2 = (const float*)d_in[4];
    const float* b2 = (const float*)d_in[5];
    const float* W3 = (const float*)d_in[6];
    const float* b3 = (const float*)d_in[7];
    float* out = (float*)d_out;
    (void)in_sizes; (void)n_in; (void)out_size;

    prep_kernel<<<320, 256>>>(g, W1, W2);
    w1q_kernel<<<HP, 32>>>();
    hihj2_kernel<<<dim3(64, 2), 256>>>(g, W1, b1);

    cudaFuncSetAttribute(pair_i8, cudaFuncAttributeMaxDynamicSharedMemorySize, SMEM_BYTES);
    pair_i8<<<dim3(640, 1, BB), 256, SMEM_BYTES>>>(m, b2, W3, b3, out);
}

// round 16
// speedup vs baseline: 3.1714x; 3.1714x over previous
#include <cuda_runtime.h>
#include <cuda_fp16.h>
#include <cstdint>

#define BB 2
#define NN 256
#define EE 512
#define HH 150
#define HP 160

// smem map (bytes). K=64 chunks: stage = A [64 x 128B swz] + B [160 x 128B swz]
#define STG_SZ  28672
#define SM_STG  0        // 2 stages = 57344 (dead after GEMM1)
#define SM_W2   0        // phase2: W2T fp16 [160 x 336B] = 53760 (reuses stages)
#define SM_HF   57344    // 64 x 336B = 21504
#define SM_HT   78848    // 21504 (end 100352)
#define SM_GIH  100352   // g_i fp16 [512] = 1024
#define SM_HI   101376   // fp32[160]
#define SM_HJC  102016   // fp32[160]
#define SM_B2   102656
#define SM_W3   103296
#define SM_PRB  103936   // 4 x 64 fp32 (end 104960)
#define SMEM_BYTES 104960

// device scratch
__device__ __half d_gh[BB * NN * EE];     // fp16 g
__device__ __half d_W1cTh[HP * EE];       // W1c^T [n][k] fp16, zero-padded
__device__ __half d_W2Th[HP * HP];        // W2^T fp16, zero-padded
__device__ float  d_hi[BB * NN * HP];     // g@W1a + b1 (fp32)
__device__ float  d_hj[BB * NN * HP];     // g@W1b (fp32 accum)
__device__ __half d_hjh[BB * NN * HP];
__device__ __half d_hih[BB * NN * HP];

// ---- helpers ----
__device__ __forceinline__ uint32_t h2mul(uint32_t a, uint32_t b) {
    uint32_t r; asm("mul.rn.f16x2 %0, %1, %2;" : "=r"(r) : "r"(a), "r"(b)); return r;
}
__device__ __forceinline__ float2 h2f2(uint32_t h) {
    __half2 v = *reinterpret_cast<__half2*>(&h); return __half22float2(v);
}
__device__ __forceinline__ uint32_t f2h2(float lo, float hi) {
    uint32_t r; asm("cvt.rn.f16x2.f32 %0, %1, %2;" : "=r"(r) : "f"(hi), "f"(lo)); return r;
}
__device__ __forceinline__ void cp16s(uint32_t dst, const void* src) {
    asm volatile("cp.async.cg.shared.global [%0], [%1], 16;" :: "r"(dst), "l"(src));
}
__device__ __forceinline__ void sts32(uint32_t a, uint32_t v) {
    asm volatile("st.shared.b32 [%0], %1;" :: "r"(a), "r"(v));
}
__device__ __forceinline__ uint32_t lds32(uint32_t a) {
    uint32_t v; asm volatile("ld.shared.b32 %0, [%1];" : "=r"(v) : "r"(a)); return v;
}
#define LDSM4(r0, r1, r2, r3, a)                                              \
    asm volatile("ldmatrix.sync.aligned.m8n8.x4.shared.b16 {%0,%1,%2,%3}, [%4];" \
                 : "=r"(r0), "=r"(r1), "=r"(r2), "=r"(r3) : "r"(a))
#define LDSM2(r0, r1, a)                                                      \
    asm volatile("ldmatrix.sync.aligned.m8n8.x2.shared.b16 {%0,%1}, [%2];"    \
                 : "=r"(r0), "=r"(r1) : "r"(a))
__device__ __forceinline__ void mma16(float* d, const uint32_t* a, const uint32_t* b) {
    asm volatile("mma.sync.aligned.m16n8k16.row.col.f32.f16.f16.f32 "
                 "{%0,%1,%2,%3},{%4,%5,%6,%7},{%8,%9},{%0,%1,%2,%3};"
                 : "+f"(d[0]), "+f"(d[1]), "+f"(d[2]), "+f"(d[3])
                 : "r"(a[0]), "r"(a[1]), "r"(a[2]), "r"(a[3]), "r"(b[0]), "r"(b[1]));
}

// ---------------------------------------------------------------------------
// prep: fp16 conversions + hi(=b1)/hj(=0) init (R10-measured structure)
// ---------------------------------------------------------------------------
__global__ void prep_kernel(const float* __restrict__ g, const float* __restrict__ W1,
                            const float* __restrict__ W2, const float* __restrict__ b1) {
    const int S0 = BB * NN * EE, S1 = HP * EE, S2 = HP * HP, S4 = BB * NN * HP;
    const int total = S0 + S1 + S2 + S4 + S4;
    for (int idx = blockIdx.x * blockDim.x + threadIdx.x; idx < total;
         idx += gridDim.x * blockDim.x) {
        int t = idx;
        if (t < S0) { d_gh[t] = __float2half(g[t]); continue; }
        t -= S0;
        if (t < S1) {
            int n = t >> 9, k = t & 511;
            d_W1cTh[t] = (n < HH) ? __float2half(W1[(size_t)(2 * EE + k) * HH + n])
                                  : __float2half(0.f);
            continue;
        }
        t -= S1;
        if (t < S2) {
            int n = t / HP, k = t % HP;
            d_W2Th[t] = (n < HH && k < HH) ? __float2half(W2[(size_t)k * HH + n])
                                           : __float2half(0.f);
            continue;
        }
        t -= S2;
        if (t < S4) { int c = t % HP; d_hi[t] = (c < HH) ? b1[c] : 0.f; continue; }
        t -= S4;
        d_hj[t] = 0.f;
    }
}

// ---------------------------------------------------------------------------
// hi/hj: K-split x4 + atomicAdd (128 blocks — the measured-fast version)
// ---------------------------------------------------------------------------
__global__ void hihj_kernel(const float* __restrict__ g, const float* __restrict__ W1) {
    __shared__ float gs[32][33];
    __shared__ float Ws[32][HP];
    const int tid = threadIdx.x;
    const int kz = blockIdx.x, rb = blockIdx.y, half = blockIdx.z;
    const int row0 = rb * 32, k0 = kz * 128;
    const int ty = tid >> 4, tx = tid & 15;
    float acc[2][10];
#pragma unroll
    for (int u = 0; u < 2; u++)
#pragma unroll
        for (int v = 0; v < 10; v++) acc[u][v] = 0.f;
    for (int kk = 0; kk < 4; kk++) {
        const int kbase = k0 + kk * 32;
        for (int q = tid; q < 32 * 32; q += 256) {
            int r = q >> 5, c = q & 31;
            gs[r][c] = g[(size_t)(row0 + r) * EE + kbase + c];
        }
        for (int q = tid; q < 32 * HP; q += 256) {
            int r = q / HP, c = q % HP;
            Ws[r][c] = (c < HH) ? W1[(size_t)(half * 512 + kbase + r) * HH + c] : 0.f;
        }
        __syncthreads();
#pragma unroll 4
        for (int k = 0; k < 32; k++) {
            float g0 = gs[ty * 2][k], g1 = gs[ty * 2 + 1][k];
#pragma unroll
            for (int v = 0; v < 10; v++) {
                float w = Ws[k][tx * 10 + v];
                acc[0][v] += g0 * w;
                acc[1][v] += g1 * w;
            }
        }
        __syncthreads();
    }
    float* dst = half ? d_hj : d_hi;
#pragma unroll
    for (int u = 0; u < 2; u++)
#pragma unroll
        for (int v = 0; v < 10; v++)
            atomicAdd(&dst[(size_t)(row0 + ty * 2 + u) * HP + tx * 10 + v], acc[u][v]);
}

__global__ void cvt_hj_kernel() {
    int t = blockIdx.x * 256 + threadIdx.x;
    if (t < BB * NN * HP) {
        d_hjh[t] = __float2half(d_hj[t]);
        d_hih[t] = __float2half(d_hi[t]);
    }
}

// ---------------------------------------------------------------------------
// fused kernel: fp16 GEMM1 in 8 K=64 chunks (2-stage, swizzled 128B rows,
// A-fragment g_i scaling), fp16 GEMM2, symmetric hij reuse.
// 256 threads, 8 warps 2Mx4N, 2 CTAs/SM.
// ---------------------------------------------------------------------------
__global__ __launch_bounds__(256, 2) void pair_fp16(
    const float* __restrict__ ment, const float* __restrict__ b2,
    const float* __restrict__ W3, const float* __restrict__ b3,
    float* __restrict__ out) {
    extern __shared__ __align__(16) unsigned char smem[];
    const uint32_t sb = (uint32_t)__cvta_generic_to_shared(smem);
    float* hi_s  = (float*)(smem + SM_HI);
    float* hjc_s = (float*)(smem + SM_HJC);
    float* b2_s  = (float*)(smem + SM_B2);
    float* w3_s  = (float*)(smem + SM_W3);
    float* prb   = (float*)(smem + SM_PRB);

    const int tid = threadIdx.x, wid = tid >> 5, lane = tid & 31;
    const int b = blockIdx.z;
    int t = blockIdx.x, jb, i;
    if (t < 64)       { jb = 0; i = t; }
    else if (t < 192) { jb = 1; i = t - 64; }
    else if (t < 384) { jb = 2; i = t - 192; }
    else              { jb = 3; i = t - 384; }
    const int j0 = jb * 64;
    const bool has_t = (i < j0);
    const int wm = wid >> 2, wn = wid & 3, grp = lane >> 2, tig = lane & 3;

    const __half* gj = d_gh + (size_t)(b * NN + j0) * EE;
    const __half* gi = d_gh + (size_t)(b * NN + i) * EE;

    // ---- prologue: gi + stages 0,1 ----
    if (tid < 64) cp16s(sb + SM_GIH + tid * 16, gi + tid * 8);
#pragma unroll
    for (int c = 0; c < 2; c++) {
        const uint32_t stg = sb + SM_STG + c * STG_SZ;
#pragma unroll
        for (int q = 0; q < 2; q++) {        // A: 64 rows x 8 segs = 512 cp16
            int p = tid + q * 256;
            int row = p >> 3, seg = p & 7;
            cp16s(stg + row * 128 + ((seg * 16) ^ ((row & 7) << 4)),
                  gj + (size_t)row * EE + c * 64 + seg * 8);
        }
#pragma unroll
        for (int q = 0; q < 5; q++) {        // B: 160 rows x 8 segs = 1280 cp16
            int p = tid + q * 256;
            int row = p >> 3, seg = p & 7;
            cp16s(stg + 8192 + row * 128 + ((seg * 16) ^ ((row & 7) << 4)),
                  d_W1cTh + (size_t)row * EE + c * 64 + seg * 8);
        }
        asm volatile("cp.async.commit_group;");
    }

    for (int q = tid; q < HP; q += 256) {
        hi_s[q]  = d_hi[(size_t)(b * NN + i) * HP + q];
        hjc_s[q] = d_hj[(size_t)(b * NN + i) * HP + q];
        b2_s[q]  = (q < HH) ? b2[q] : 0.f;
        w3_s[q]  = (q < HH) ? W3[q] : 0.f;
    }

    // fragment addressing (byte-geometry validated in R12)
    const uint32_t armA  = (uint32_t)(wm * 32 + (lane & 7) + ((lane >> 3) & 1) * 8);
    const uint32_t amask = (armA & 7) << 4;
    const uint32_t akof0 = (lane >> 4) * 16;
    const uint32_t brow  = (uint32_t)(wn * 40 + (lane & 7) + ((lane >> 4) & 1) * 8);
    const uint32_t bmask = (brow & 7) << 4;
    const uint32_t bkof0 = ((lane >> 3) & 1) * 16;
    const uint32_t b2row = (uint32_t)(wn * 40 + 32 + (lane & 7));
    const uint32_t b2mask = (b2row & 7) << 4;

    float acc[2][5][4];
#pragma unroll
    for (int x = 0; x < 2; x++)
#pragma unroll
        for (int y = 0; y < 5; y++)
#pragma unroll
            for (int e = 0; e < 4; e++) acc[x][y][e] = 0.f;

    // ---- GEMM1: 8 chunks (K=64) x 4 k16 steps ----
#pragma unroll 1
    for (int c = 0; c < 8; c++) {
        if (c < 7) asm volatile("cp.async.wait_group 1;");
        else       asm volatile("cp.async.wait_group 0;");
        __syncthreads();
        const uint32_t stg = sb + SM_STG + (c & 1) * STG_SZ;
        const uint32_t abase = stg + armA * 128;
        const uint32_t bbase = stg + 8192 + brow * 128;
        const uint32_t b2base = stg + 8192 + b2row * 128;
#pragma unroll
        for (int k2 = 0; k2 < 4; k2++) {
            const uint32_t g01 = lds32(sb + SM_GIH + c * 128 + k2 * 32 + tig * 4);
            const uint32_t g23 = lds32(sb + SM_GIH + c * 128 + k2 * 32 + tig * 4 + 16);
            uint32_t a[2][4], bf[5][2];
            const uint32_t ak = (k2 * 32 + akof0) ^ amask;
            LDSM4(a[0][0], a[0][1], a[0][2], a[0][3], abase + ak);
            LDSM4(a[1][0], a[1][1], a[1][2], a[1][3], abase + 16 * 128 + ak);
#pragma unroll
            for (int mt = 0; mt < 2; mt++) {
                a[mt][0] = h2mul(a[mt][0], g01);
                a[mt][1] = h2mul(a[mt][1], g01);
                a[mt][2] = h2mul(a[mt][2], g23);
                a[mt][3] = h2mul(a[mt][3], g23);
            }
            const uint32_t bk = (k2 * 32 + bkof0) ^ bmask;
            LDSM4(bf[0][0], bf[0][1], bf[1][0], bf[1][1], bbase + bk);
            LDSM4(bf[2][0], bf[2][1], bf[3][0], bf[3][1], bbase + 16 * 128 + bk);
            const uint32_t b2k = (k2 * 32 + bkof0) ^ b2mask;
            LDSM2(bf[4][0], bf[4][1], b2base + b2k);
#pragma unroll
            for (int mt = 0; mt < 2; mt++)
#pragma unroll
                for (int nt = 0; nt < 5; nt++) mma16(acc[mt][nt], a[mt], bf[nt]);
        }
        __syncthreads();
        if (c + 2 < 8) {
            const int cn = c + 2;
            const uint32_t stgn = sb + SM_STG + (cn & 1) * STG_SZ;
#pragma unroll
            for (int q = 0; q < 2; q++) {
                int p = tid + q * 256;
                int row = p >> 3, seg = p & 7;
                cp16s(stgn + row * 128 + ((seg * 16) ^ ((row & 7) << 4)),
                      gj + (size_t)row * EE + cn * 64 + seg * 8);
            }
#pragma unroll
            for (int q = 0; q < 5; q++) {
                int p = tid + q * 256;
                int row = p >> 3, seg = p & 7;
                cp16s(stgn + 8192 + row * 128 + ((seg * 16) ^ ((row & 7) << 4)),
                      d_W1cTh + (size_t)row * EE + cn * 64 + seg * 8);
            }
            asm volatile("cp.async.commit_group;");
        }
    }

    // ---- prefetch W2T into SM_W2 (overlaps epilogue1) ----
#pragma unroll
    for (int tt = 0; tt < 13; tt++) {
        int q = tid + tt * 256;
        if (q < 3200) {
            int n = q / 20, u = q % 20;
            cp16s(sb + SM_W2 + n * 336 + u * 16, d_W2Th + (size_t)n * HP + u * 8);
        }
    }
    asm volatile("cp.async.commit_group;");

    // ---- epilogue1: h = relu(acc + hi + hj) -> HF (and HT) fp16 ----
#pragma unroll
    for (int mt = 0; mt < 2; mt++) {
#pragma unroll
        for (int hrow = 0; hrow < 2; hrow++) {
            const int r = wm * 32 + mt * 16 + grp + hrow * 8;
            const __half* hjrow = d_hjh + (size_t)(b * NN + j0 + r) * HP;
            const __half* hirow = d_hih + (size_t)(b * NN + j0 + r) * HP;
#pragma unroll
            for (int nt = 0; nt < 5; nt++) {
                const int col = wn * 40 + nt * 8 + 2 * tig;
                const float a0 = acc[mt][nt][hrow * 2 + 0];
                const float a1 = acc[mt][nt][hrow * 2 + 1];
                float2 hjf = h2f2(*(const uint32_t*)(hjrow + col));
                float x0 = fmaxf(a0 + hi_s[col] + hjf.x, 0.f);
                float x1 = fmaxf(a1 + hi_s[col + 1] + hjf.y, 0.f);
                sts32(sb + SM_HF + r * 336 + col * 2, f2h2(x0, x1));
                if (has_t) {
                    float2 hif = h2f2(*(const uint32_t*)(hirow + col));
                    float y0 = fmaxf(a0 + hif.x + hjc_s[col], 0.f);
                    float y1 = fmaxf(a1 + hif.y + hjc_s[col + 1], 0.f);
                    sts32(sb + SM_HT + r * 336 + col * 2, f2h2(y0, y1));
                }
            }
        }
    }
    asm volatile("cp.async.wait_group 0;");
    __syncthreads();

    // ---- GEMM2 (fp16, W2T resident) + epilogue2, fwd then transposed ----
    const uint32_t aoffH  = armA * 336 + (lane >> 4) * 16;
    const uint32_t boff4W = brow * 336 + ((lane >> 3) & 1) * 16;
    const uint32_t boff2W = b2row * 336 + ((lane >> 3) & 1) * 16;

#pragma unroll 1
    for (int pass = 0; pass < 2; pass++) {
        if (pass == 1 && !has_t) break;
        const uint32_t hbase = sb + (pass ? SM_HT : SM_HF) + aoffH;
        float acc2[2][5][4];
#pragma unroll
        for (int x = 0; x < 2; x++)
#pragma unroll
            for (int y = 0; y < 5; y++)
#pragma unroll
                for (int e = 0; e < 4; e++) acc2[x][y][e] = 0.f;
#pragma unroll
        for (int kk = 0; kk < 10; kk++) {
            uint32_t a[2][4], bf[5][2];
            const uint32_t abase = hbase + kk * 32;
            LDSM4(a[0][0], a[0][1], a[0][2], a[0][3], abase);
            LDSM4(a[1][0], a[1][1], a[1][2], a[1][3], abase + 5376);
            const uint32_t bbw = sb + SM_W2 + kk * 32;
            LDSM4(bf[0][0], bf[0][1], bf[1][0], bf[1][1], bbw + boff4W);
            LDSM4(bf[2][0], bf[2][1], bf[3][0], bf[3][1], bbw + boff4W + 5376);
            LDSM2(bf[4][0], bf[4][1], bbw + boff2W);
#pragma unroll
            for (int mt = 0; mt < 2; mt++)
#pragma unroll
                for (int nt = 0; nt < 5; nt++) mma16(acc2[mt][nt], a[mt], bf[nt]);
        }
#pragma unroll
        for (int mt = 0; mt < 2; mt++) {
            float s0 = 0.f, s1 = 0.f;
#pragma unroll
            for (int nt = 0; nt < 5; nt++) {
                const int col = wn * 40 + nt * 8 + 2 * tig;
                s0 += fmaxf(acc2[mt][nt][0] + b2_s[col], 0.f) * w3_s[col];
                s0 += fmaxf(acc2[mt][nt][1] + b2_s[col + 1], 0.f) * w3_s[col + 1];
                s1 += fmaxf(acc2[mt][nt][2] + b2_s[col], 0.f) * w3_s[col];
                s1 += fmaxf(acc2[mt][nt][3] + b2_s[col + 1], 0.f) * w3_s[col + 1];
            }
            s0 += __shfl_xor_sync(0xffffffffu, s0, 1);
            s0 += __shfl_xor_sync(0xffffffffu, s0, 2);
            s1 += __shfl_xor_sync(0xffffffffu, s1, 1);
            s1 += __shfl_xor_sync(0xffffffffu, s1, 2);
            if (tig == 0) {
                prb[wn * 64 + wm * 32 + mt * 16 + grp] = s0;
                prb[wn * 64 + wm * 32 + mt * 16 + grp + 8] = s1;
            }
        }
        __syncthreads();
        if (tid < 64) {
            const int j = j0 + tid;
            float pair = prb[tid] + prb[64 + tid] + prb[128 + tid] + prb[192 + tid] + b3[0];
            float mi = ment[b * NN + i];
            float mj = ment[b * NN + j];
            float val = (mi + mj + pair) * (1.f / 3.f);
            if (pass == 0) out[(size_t)(b * NN + i) * NN + j] = val;
            else           out[(size_t)(b * NN + j) * NN + i] = val;
        }
        __syncthreads();
    }
}

// ---------------------------------------------------------------------------
extern "C" void kernel_launch(void* const* d_in, const int* in_sizes, int n_in,
                              void* d_out, int out_size) {
    const float* g  = (const float*)d_in[0];
    const float* m  = (const float*)d_in[1];
    const float* W1 = (const float*)d_in[2];
    const float* b1 = (const float*)d_in[3];
    const float* W2 = (const float*)d_in[4];
    const float* b2 = (const float*)d_in[5];
    const float* W3 = (const float*)d_in[6];
    const float* b3 = (const float*)d_in[7];
    float* out = (float*)d_out;
    (void)in_sizes; (void)n_in; (void)out_size;

    prep_kernel<<<544, 256>>>(g, W1, W2, b1);
    hihj_kernel<<<dim3(4, 16, 2), 256>>>(g, W1);
    cvt_hj_kernel<<<320, 256>>>();

    cudaFuncSetAttribute(pair_fp16, cudaFuncAttributeMaxDynamicSharedMemorySize, SMEM_BYTES);
    pair_fp16<<<dim3(640, 1, BB), 256, SMEM_BYTES>>>(m, b2, W3, b3, out);
}